// round 3
// baseline (speedup 1.0000x reference)
#include <cuda_runtime.h>
#include <cstdint>
#include <cstddef>

// ---------------------------------------------------------------------------
// WaveNet forward, fp32.
// h layout: [b][t][c] (c contiguous).  G layout: [b][u][layer*32+c].
// Pipeline: in_conv -> 50x layer_kernel (ping-pong h, write G)
//           -> skip GEMM (G @ Wskip^T + sum(b_skip))
//           -> post1 GEMM (elu in, elu out) -> post2 dot.
// ---------------------------------------------------------------------------

#define T_LEN   8192
#define NRES    32
#define NSKIP   512
#define NFEAT   8
#define NLAY    50
#define OUTLEN  3077
#define BATCH   8
#define LTS     96          // timesteps per layer-kernel block
#define MROWS   (BATCH * OUTLEN)   // 24616

// ------------------------- device scratch (static) -------------------------
__device__ float g_hA[(size_t)BATCH * T_LEN * NRES];        // 8.4 MB
__device__ float g_hB[(size_t)BATCH * T_LEN * NRES];        // 8.4 MB
__device__ float g_G[(size_t)MROWS * NLAY * NRES];          // 157.5 MB
__device__ float g_skip[(size_t)MROWS * NSKIP];             // 50.4 MB
__device__ float g_y2[(size_t)MROWS * NSKIP];               // 50.4 MB
__device__ float g_Wskip[(size_t)NLAY * NRES * NSKIP];      // [k][s], 3.3 MB
__device__ float g_bskip[NSKIP];
__device__ float g_Wp1T[(size_t)NSKIP * NSKIP];             // [c][o], 1 MB

// ------------------------------ helpers ------------------------------------
__device__ __forceinline__ float2 ffma2(float2 a, float2 b, float2 c) {
    float2 d;
    asm("fma.rn.f32x2 %0, %1, %2, %3;"
        : "=l"(*reinterpret_cast<unsigned long long*>(&d))
        : "l"(*reinterpret_cast<unsigned long long*>(&a)),
          "l"(*reinterpret_cast<unsigned long long*>(&b)),
          "l"(*reinterpret_cast<unsigned long long*>(&c)));
    return d;
}

__device__ __forceinline__ float sigmoid_f(float x) {
    x = fminf(fmaxf(x, -30.f), 30.f);
    return __fdividef(1.f, 1.f + __expf(-x));
}
__device__ __forceinline__ float tanh_f(float x) {
    x = fminf(fmaxf(x, -15.f), 15.f);
    float e = __expf(-2.f * x);
    return __fdividef(1.f - e, 1.f + e);
}
__device__ __forceinline__ float eluf(float x) {
    return x > 0.f ? x : (__expf(x) - 1.f);
}

// ------------------------------ input conv ---------------------------------
// h[b][t][o] = sum_f w_in[o][f] * x[b][t][f] + b_in[o]
__global__ __launch_bounds__(256) void in_conv_kernel(
    const float* __restrict__ x, const float* __restrict__ w_in,
    const float* __restrict__ b_in)
{
    int b = blockIdx.y;
    int t = blockIdx.x * 8 + (threadIdx.x >> 5);
    int o = threadIdx.x & 31;
    float w[NFEAT];
#pragma unroll
    for (int f = 0; f < NFEAT; ++f) w[f] = w_in[o * NFEAT + f];
    const float* xp = x + ((size_t)b * T_LEN + t) * NFEAT;
    float acc = b_in[o];
#pragma unroll
    for (int f = 0; f < NFEAT; ++f) acc = fmaf(w[f], xp[f], acc);
    g_hA[((size_t)b * T_LEN + t) * NRES + o] = acc;
}

// ------------------------------ repacks ------------------------------------
// g_Wskip[k][s] = w_skip[i][s][c],  k = i*32+c
__global__ __launch_bounds__(256) void repack_wskip_kernel(const float* __restrict__ w_skip)
{
    int idx = blockIdx.x * 256 + threadIdx.x;       // < 1600*512
    int k = idx >> 9, s = idx & 511;
    g_Wskip[idx] = w_skip[((size_t)(k >> 5) * NSKIP + s) * NRES + (k & 31)];
}
__global__ __launch_bounds__(256) void bias_sum_kernel(const float* __restrict__ b_skip)
{
    int s = blockIdx.x * 256 + threadIdx.x;
    if (s < NSKIP) {
        float a = 0.f;
#pragma unroll
        for (int i = 0; i < NLAY; ++i) a += b_skip[i * NSKIP + s];
        g_bskip[s] = a;
    }
}
__global__ __launch_bounds__(256) void repack_wpost1_kernel(const float* __restrict__ w_post1)
{
    int idx = blockIdx.x * 256 + threadIdx.x;       // < 512*512
    int c = idx >> 9, o = idx & 511;
    g_Wp1T[idx] = w_post1[(size_t)o * NSKIP + c];
}

// ------------------------------ layer kernel -------------------------------
__global__ __launch_bounds__(256) void layer_kernel(
    const float* __restrict__ w_sig, const float* __restrict__ b_sig,
    const float* __restrict__ w_tanh, const float* __restrict__ b_tanh,
    const float* __restrict__ w_res, const float* __restrict__ b_res,
    int layer, int d, int Lout, int goff, int ping)
{
    __shared__ float ws0[32][33], ws1[32][33], wt0[32][33], wt1[32][33], wrs[32][33];
    __shared__ float bs[32], bt[32], br[32];
    __shared__ float h0s[LTS][32], h1s[LTS][32];

    const float* h_in = ping ? g_hB : g_hA;
    float* h_out      = ping ? g_hA : g_hB;

    int tid = threadIdx.x;
    int b = blockIdx.y;
    int t0 = blockIdx.x * LTS;

    // weights -> shared, transposed to [c][o]
    const float* wsp = w_sig  + (size_t)layer * 2048;
    const float* wtp = w_tanh + (size_t)layer * 2048;
    const float* wrp = w_res  + (size_t)layer * 1024;
#pragma unroll
    for (int p = tid; p < 1024; p += 256) {
        int o = p >> 5, c = p & 31;
        ws0[c][o] = wsp[2 * p];     ws1[c][o] = wsp[2 * p + 1];
        wt0[c][o] = wtp[2 * p];     wt1[c][o] = wtp[2 * p + 1];
        wrs[c][o] = wrp[p];
    }
    if (tid < 32) {
        bs[tid] = b_sig[layer * 32 + tid];
        bt[tid] = b_tanh[layer * 32 + tid];
        br[tid] = b_res[layer * 32 + tid];
    }

    const float* hb = h_in + (size_t)b * T_LEN * NRES;
    for (int idx = tid; idx < LTS * 32; idx += 256) {
        int j = idx >> 5;
        int c = idx & 31;
        int t = t0 + j;
        float v0 = 0.f, v1 = 0.f;
        if (t < Lout) {
            v0 = hb[(size_t)t * NRES + c];
            v1 = hb[(size_t)(t + d) * NRES + c];
        }
        (&h0s[0][0])[idx] = v0;
        (&h1s[0][0])[idx] = v1;
    }
    __syncthreads();

    int w = tid >> 5, o = tid & 31;
    float* Gb  = g_G + (size_t)b * OUTLEN * (NLAY * NRES) + (size_t)layer * NRES;
    float* hob = h_out + (size_t)b * T_LEN * NRES;

#pragma unroll
    for (int grp = 0; grp < 3; ++grp) {
        int jb = w * 12 + grp * 4;
        float ps0 = bs[o], ps1 = ps0, ps2 = ps0, ps3 = ps0;
        float pt0 = bt[o], pt1 = pt0, pt2 = pt0, pt3 = pt0;
#pragma unroll
        for (int c = 0; c < 32; ++c) {
            float W0 = ws0[c][o], W1 = ws1[c][o];
            float V0 = wt0[c][o], V1 = wt1[c][o];
            float a0 = h0s[jb + 0][c], a1 = h0s[jb + 1][c];
            float a2 = h0s[jb + 2][c], a3 = h0s[jb + 3][c];
            float e0 = h1s[jb + 0][c], e1 = h1s[jb + 1][c];
            float e2 = h1s[jb + 2][c], e3 = h1s[jb + 3][c];
            ps0 = fmaf(W0, a0, ps0); ps1 = fmaf(W0, a1, ps1);
            ps2 = fmaf(W0, a2, ps2); ps3 = fmaf(W0, a3, ps3);
            ps0 = fmaf(W1, e0, ps0); ps1 = fmaf(W1, e1, ps1);
            ps2 = fmaf(W1, e2, ps2); ps3 = fmaf(W1, e3, ps3);
            pt0 = fmaf(V0, a0, pt0); pt1 = fmaf(V0, a1, pt1);
            pt2 = fmaf(V0, a2, pt2); pt3 = fmaf(V0, a3, pt3);
            pt0 = fmaf(V1, e0, pt0); pt1 = fmaf(V1, e1, pt1);
            pt2 = fmaf(V1, e2, pt2); pt3 = fmaf(V1, e3, pt3);
        }
        float g0 = sigmoid_f(ps0) * tanh_f(pt0);
        float g1 = sigmoid_f(ps1) * tanh_f(pt1);
        float g2 = sigmoid_f(ps2) * tanh_f(pt2);
        float g3 = sigmoid_f(ps3) * tanh_f(pt3);

        float r0 = br[o] + h1s[jb + 0][o];
        float r1 = br[o] + h1s[jb + 1][o];
        float r2 = br[o] + h1s[jb + 2][o];
        float r3 = br[o] + h1s[jb + 3][o];
#pragma unroll
        for (int c = 0; c < 32; ++c) {
            float wv = wrs[c][o];
            r0 = fmaf(wv, __shfl_sync(0xffffffffu, g0, c), r0);
            r1 = fmaf(wv, __shfl_sync(0xffffffffu, g1, c), r1);
            r2 = fmaf(wv, __shfl_sync(0xffffffffu, g2, c), r2);
            r3 = fmaf(wv, __shfl_sync(0xffffffffu, g3, c), r3);
        }
        {
            int t = t0 + jb + 0;
            if (t < Lout) {
                hob[(size_t)t * NRES + o] = r0;
                int u = t - goff;
                if (u >= 0) Gb[(size_t)u * (NLAY * NRES) + o] = g0;
            }
        }
        {
            int t = t0 + jb + 1;
            if (t < Lout) {
                hob[(size_t)t * NRES + o] = r1;
                int u = t - goff;
                if (u >= 0) Gb[(size_t)u * (NLAY * NRES) + o] = g1;
            }
        }
        {
            int t = t0 + jb + 2;
            if (t < Lout) {
                hob[(size_t)t * NRES + o] = r2;
                int u = t - goff;
                if (u >= 0) Gb[(size_t)u * (NLAY * NRES) + o] = g2;
            }
        }
        {
            int t = t0 + jb + 3;
            if (t < Lout) {
                hob[(size_t)t * NRES + o] = r3;
                int u = t - goff;
                if (u >= 0) Gb[(size_t)u * (NLAY * NRES) + o] = g3;
            }
        }
    }
}

// ------------------------------ GEMM core ----------------------------------
// C[M x 512] = A[M x KDIM] * B[KDIM x 512] (+ bias), optional elu on A load
// and elu on output.  BM=128, BN=64, BK=16, 256 threads, 8x4 per thread via
// f32x2 FFMA2 (m-pairs x dup-n).
template <int KDIM, bool ELU_IN, bool ELU_OUT>
__device__ __forceinline__ void gemm_core(
    const float* __restrict__ A, const float* __restrict__ Bm,
    const float* __restrict__ bias, float* __restrict__ Cout, int M)
{
    const int N = 512;
    __shared__ float  As[16][128];
    __shared__ float2 Bsd[16][64];

    int tid = threadIdx.x;
    int mBase = blockIdx.x * 128;
    int nBase = blockIdx.y * 64;
    int m0 = (tid & 15) * 8;
    int n0 = (tid >> 4) * 4;

    float2 acc[4][4];
#pragma unroll
    for (int i = 0; i < 4; ++i)
#pragma unroll
        for (int j = 0; j < 4; ++j) acc[i][j] = make_float2(0.f, 0.f);

    int ar = tid >> 1;            // 0..127
    int ac = (tid & 1) * 8;       // 0 or 8
    int bk = tid >> 4;            // 0..15
    int bn = (tid & 15) * 4;      // 0..60

    for (int kt = 0; kt < KDIM; kt += 16) {
        // A tile (transposed into As[k][m])
        int row = mBase + ar;
        float4 v0, v1;
        if (row < M) {
            const float4* src = reinterpret_cast<const float4*>(
                A + (size_t)row * KDIM + kt + ac);
            v0 = src[0];
            v1 = src[1];
        } else {
            v0 = make_float4(0.f, 0.f, 0.f, 0.f);
            v1 = v0;
        }
        if (ELU_IN) {
            v0.x = eluf(v0.x); v0.y = eluf(v0.y); v0.z = eluf(v0.z); v0.w = eluf(v0.w);
            v1.x = eluf(v1.x); v1.y = eluf(v1.y); v1.z = eluf(v1.z); v1.w = eluf(v1.w);
        }
        As[ac + 0][ar] = v0.x; As[ac + 1][ar] = v0.y;
        As[ac + 2][ar] = v0.z; As[ac + 3][ar] = v0.w;
        As[ac + 4][ar] = v1.x; As[ac + 5][ar] = v1.y;
        As[ac + 6][ar] = v1.z; As[ac + 7][ar] = v1.w;

        // B tile, duplicated pairs
        float4 bv = *reinterpret_cast<const float4*>(
            Bm + (size_t)(kt + bk) * N + nBase + bn);
        float4* bd = reinterpret_cast<float4*>(&Bsd[bk][bn]);
        bd[0] = make_float4(bv.x, bv.x, bv.y, bv.y);
        bd[1] = make_float4(bv.z, bv.z, bv.w, bv.w);

        __syncthreads();
#pragma unroll
        for (int k = 0; k < 16; ++k) {
            float4 a0 = *reinterpret_cast<const float4*>(&As[k][m0]);
            float4 a1 = *reinterpret_cast<const float4*>(&As[k][m0 + 4]);
            float4 b0 = *reinterpret_cast<const float4*>(&Bsd[k][n0]);
            float4 b1 = *reinterpret_cast<const float4*>(&Bsd[k][n0 + 2]);
            float2 ap[4] = { {a0.x, a0.y}, {a0.z, a0.w}, {a1.x, a1.y}, {a1.z, a1.w} };
            float2 bq[4] = { {b0.x, b0.y}, {b0.z, b0.w}, {b1.x, b1.y}, {b1.z, b1.w} };
#pragma unroll
            for (int i = 0; i < 4; ++i)
#pragma unroll
                for (int j = 0; j < 4; ++j)
                    acc[i][j] = ffma2(ap[i], bq[j], acc[i][j]);
        }
        __syncthreads();
    }

    float b4[4];
#pragma unroll
    for (int j = 0; j < 4; ++j) b4[j] = bias[nBase + n0 + j];

#pragma unroll
    for (int i = 0; i < 4; ++i) {
        int r0 = mBase + m0 + 2 * i;
        float4 o0 = make_float4(acc[i][0].x + b4[0], acc[i][1].x + b4[1],
                                acc[i][2].x + b4[2], acc[i][3].x + b4[3]);
        float4 o1 = make_float4(acc[i][0].y + b4[0], acc[i][1].y + b4[1],
                                acc[i][2].y + b4[2], acc[i][3].y + b4[3]);
        if (ELU_OUT) {
            o0.x = eluf(o0.x); o0.y = eluf(o0.y); o0.z = eluf(o0.z); o0.w = eluf(o0.w);
            o1.x = eluf(o1.x); o1.y = eluf(o1.y); o1.z = eluf(o1.z); o1.w = eluf(o1.w);
        }
        if (r0 < M)
            *reinterpret_cast<float4*>(Cout + (size_t)r0 * N + nBase + n0) = o0;
        if (r0 + 1 < M)
            *reinterpret_cast<float4*>(Cout + (size_t)(r0 + 1) * N + nBase + n0) = o1;
    }
}

__global__ __launch_bounds__(256) void skip_gemm_kernel(int M)
{
    gemm_core<NLAY * NRES, false, false>(g_G, g_Wskip, g_bskip, g_skip, M);
}
__global__ __launch_bounds__(256) void post1_gemm_kernel(const float* __restrict__ b_post1, int M)
{
    gemm_core<NSKIP, true, true>(g_skip, g_Wp1T, b_post1, g_y2, M);
}

// ------------------------------ post2 --------------------------------------
__global__ __launch_bounds__(256) void post2_kernel(
    const float* __restrict__ w2, const float* __restrict__ b2,
    float* __restrict__ out, int M)
{
    int gw = (blockIdx.x * 256 + threadIdx.x) >> 5;
    int lane = threadIdx.x & 31;
    if (gw >= M) return;
    const float* row = g_y2 + (size_t)gw * NSKIP;
    float acc = 0.f;
#pragma unroll
    for (int k = 0; k < 16; ++k)
        acc = fmaf(row[lane + 32 * k], w2[lane + 32 * k], acc);
#pragma unroll
    for (int s = 16; s > 0; s >>= 1)
        acc += __shfl_xor_sync(0xffffffffu, acc, s);
    if (lane == 0) out[gw] = acc + b2[0];
}

// ------------------------------ launch -------------------------------------
extern "C" void kernel_launch(void* const* d_in, const int* in_sizes, int n_in,
                              void* d_out, int out_size)
{
    const float* x       = (const float*)d_in[0];
    const float* w_in    = (const float*)d_in[1];
    const float* b_in    = (const float*)d_in[2];
    const float* w_sig   = (const float*)d_in[3];
    const float* b_sig   = (const float*)d_in[4];
    const float* w_tanh  = (const float*)d_in[5];
    const float* b_tanh  = (const float*)d_in[6];
    const float* w_skip  = (const float*)d_in[7];
    const float* b_skip  = (const float*)d_in[8];
    const float* w_res   = (const float*)d_in[9];
    const float* b_res   = (const float*)d_in[10];
    const float* w_post1 = (const float*)d_in[11];
    const float* b_post1 = (const float*)d_in[12];
    const float* w_post2 = (const float*)d_in[13];
    const float* b_post2 = (const float*)d_in[14];
    float* out = (float*)d_out;

    // input 1x1 conv -> g_hA
    in_conv_kernel<<<dim3(T_LEN / 8, BATCH), 256>>>(x, w_in, b_in);

    // weight repacks (independent, tiny)
    repack_wskip_kernel<<<(NLAY * NRES * NSKIP) / 256, 256>>>(w_skip);
    bias_sum_kernel<<<2, 256>>>(b_skip);
    repack_wpost1_kernel<<<(NSKIP * NSKIP) / 256, 256>>>(w_post1);

    static const int dil10[10] = {1, 2, 4, 8, 16, 32, 64, 128, 256, 512};
    int L = T_LEN;
    for (int i = 0; i < NLAY; ++i) {
        int d = dil10[i % 10];
        int Lout = L - d;
        int goff = Lout - OUTLEN;
        int nb = (Lout + LTS - 1) / LTS;
        layer_kernel<<<dim3(nb, BATCH), 256>>>(w_sig, b_sig, w_tanh, b_tanh,
                                               w_res, b_res, i, d, Lout, goff, i & 1);
        L = Lout;
    }

    int M = MROWS;
    dim3 ggrid((M + 127) / 128, NSKIP / 64);
    skip_gemm_kernel<<<ggrid, 256>>>(M);
    post1_gemm_kernel<<<ggrid, 256>>>(b_post1, M);
    post2_kernel<<<(M + 7) / 8, 256>>>(w_post2, b_post2, out, M);
}

// round 4
// speedup vs baseline: 1.0233x; 1.0233x over previous
#include <cuda_runtime.h>
#include <cstdint>
#include <cstddef>

// ---------------------------------------------------------------------------
// WaveNet forward, fp32, FFMA2-centric.
// h layout: [b][t][c] (c contiguous).  G layout: [b][u][layer*32+c].
// in_conv -> 50x layer_kernel (time-pair f32x2, dup weights, ping-pong h)
//         -> skip GEMM (double-buffered, f32x2) -> post1 GEMM -> post2 dot.
// ---------------------------------------------------------------------------

#define T_LEN   8192
#define NRES    32
#define NSKIP   512
#define NFEAT   8
#define NLAY    50
#define OUTLEN  3077
#define BATCH   8
#define LTS     96                    // timesteps per layer-kernel block
#define MROWS   (BATCH * OUTLEN)      // 24616

// ------------------------- device scratch (static) -------------------------
__device__ float g_hA[(size_t)BATCH * T_LEN * NRES];
__device__ float g_hB[(size_t)BATCH * T_LEN * NRES];
__device__ float g_G[(size_t)MROWS * NLAY * NRES];
__device__ float g_skip[(size_t)MROWS * NSKIP];
__device__ float g_y2[(size_t)MROWS * NSKIP];
__device__ float g_Wskip[(size_t)NLAY * NRES * NSKIP];      // [k][s]
__device__ float g_bskip[NSKIP];
__device__ float g_Wp1T[(size_t)NSKIP * NSKIP];             // [c][o]

// ------------------------------ helpers ------------------------------------
__device__ __forceinline__ float2 ffma2(float2 a, float2 b, float2 c) {
    float2 d;
    asm("fma.rn.f32x2 %0, %1, %2, %3;"
        : "=l"(*reinterpret_cast<unsigned long long*>(&d))
        : "l"(*reinterpret_cast<unsigned long long*>(&a)),
          "l"(*reinterpret_cast<unsigned long long*>(&b)),
          "l"(*reinterpret_cast<unsigned long long*>(&c)));
    return d;
}
__device__ __forceinline__ float2 f2(float x, float y) { return make_float2(x, y); }

__device__ __forceinline__ float sigmoid_f(float x) {
    x = fminf(fmaxf(x, -30.f), 30.f);
    return __fdividef(1.f, 1.f + __expf(-x));
}
__device__ __forceinline__ float tanh_f(float x) {
    x = fminf(fmaxf(x, -15.f), 15.f);
    float e = __expf(-2.f * x);
    return __fdividef(1.f - e, 1.f + e);
}
__device__ __forceinline__ float eluf(float x) {
    return x > 0.f ? x : (__expf(x) - 1.f);
}

// ------------------------------ input conv ---------------------------------
__global__ __launch_bounds__(256) void in_conv_kernel(
    const float* __restrict__ x, const float* __restrict__ w_in,
    const float* __restrict__ b_in)
{
    int b = blockIdx.y;
    int t = blockIdx.x * 8 + (threadIdx.x >> 5);
    int o = threadIdx.x & 31;
    float w[NFEAT];
#pragma unroll
    for (int f = 0; f < NFEAT; ++f) w[f] = w_in[o * NFEAT + f];
    const float* xp = x + ((size_t)b * T_LEN + t) * NFEAT;
    float acc = b_in[o];
#pragma unroll
    for (int f = 0; f < NFEAT; ++f) acc = fmaf(w[f], xp[f], acc);
    g_hA[((size_t)b * T_LEN + t) * NRES + o] = acc;
}

// ------------------------------ repacks ------------------------------------
__global__ __launch_bounds__(256) void repack_wskip_kernel(const float* __restrict__ w_skip)
{
    int idx = blockIdx.x * 256 + threadIdx.x;       // < 1600*512
    int k = idx >> 9, s = idx & 511;
    g_Wskip[idx] = w_skip[((size_t)(k >> 5) * NSKIP + s) * NRES + (k & 31)];
}
__global__ __launch_bounds__(256) void bias_sum_kernel(const float* __restrict__ b_skip)
{
    int s = blockIdx.x * 256 + threadIdx.x;
    if (s < NSKIP) {
        float a = 0.f;
#pragma unroll
        for (int i = 0; i < NLAY; ++i) a += b_skip[i * NSKIP + s];
        g_bskip[s] = a;
    }
}
__global__ __launch_bounds__(256) void repack_wpost1_kernel(const float* __restrict__ w_post1)
{
    int idx = blockIdx.x * 256 + threadIdx.x;       // < 512*512
    int c = idx >> 9, o = idx & 511;
    g_Wp1T[idx] = w_post1[(size_t)o * NSKIP + c];
}

// ------------------------------ layer kernel -------------------------------
// dynamic smem layout (bytes):
//   wsd  [32][32] float4  (W0,W0,W1,W1)         0     .. 16384
//   wtd  [32][32] float4  (V0,V0,V1,V1)         16384 .. 32768
//   wrd  [32][32] float2  (Wr,Wr)               32768 .. 40960
//   hs0  [32][50] float2  [c][t-pair]           40960 .. 53760   (reused for g)
//   hs1  [32][50] float2                        53760 .. 66560
//   bs,bt,br [32] float each                    66560 .. 66944
#define LK_SMEM 66944
#define HS_STRIDE 50   // float2 per row

__global__ __launch_bounds__(256) void layer_kernel(
    const float* __restrict__ w_sig, const float* __restrict__ b_sig,
    const float* __restrict__ w_tanh, const float* __restrict__ b_tanh,
    const float* __restrict__ w_res, const float* __restrict__ b_res,
    int layer, int d, int Lout, int goff, int ping)
{
    extern __shared__ char smraw[];
    float4* wsd = reinterpret_cast<float4*>(smraw);                 // [c*32+o]
    float4* wtd = reinterpret_cast<float4*>(smraw + 16384);
    float2* wrd = reinterpret_cast<float2*>(smraw + 32768);
    float2* hs0 = reinterpret_cast<float2*>(smraw + 40960);         // [c*50+jp]
    float2* hs1 = reinterpret_cast<float2*>(smraw + 53760);
    float*  bs  = reinterpret_cast<float*>(smraw + 66560);
    float*  bt  = bs + 32;
    float*  br  = bs + 64;

    const float* h_in = ping ? g_hB : g_hA;
    float* h_out      = ping ? g_hA : g_hB;

    int tid = threadIdx.x;
    int b = blockIdx.y;
    int t0 = blockIdx.x * LTS;

    // ---- weights -> shared, duplicated pairs; lane = o for conflict-free writes
    const float* wsp = w_sig  + (size_t)layer * 2048;   // [o][c][tap]
    const float* wtp = w_tanh + (size_t)layer * 2048;
    const float* wrp = w_res  + (size_t)layer * 1024;   // [o][c]
#pragma unroll
    for (int p = tid; p < 1024; p += 256) {
        int o = p & 31, c = p >> 5;
        float s0 = wsp[(o * 32 + c) * 2], s1 = wsp[(o * 32 + c) * 2 + 1];
        wsd[c * 32 + o] = make_float4(s0, s0, s1, s1);
        float u0 = wtp[(o * 32 + c) * 2], u1 = wtp[(o * 32 + c) * 2 + 1];
        wtd[c * 32 + o] = make_float4(u0, u0, u1, u1);
        float r = wrp[o * 32 + c];
        wrd[c * 32 + o] = make_float2(r, r);
    }
    if (tid < 32) {
        bs[tid] = b_sig[layer * 32 + tid];
        bt[tid] = b_tanh[layer * 32 + tid];
        br[tid] = b_res[layer * 32 + tid];
    }

    // ---- h tiles -> shared, transposed to [c][t]
    const float* hb = h_in + (size_t)b * T_LEN * NRES;
    float* hs0f = reinterpret_cast<float*>(hs0);
    float* hs1f = reinterpret_cast<float*>(hs1);
    for (int idx = tid; idx < LTS * 32; idx += 256) {
        int j = idx >> 5, c = idx & 31;
        int t = t0 + j;
        float v0 = 0.f, v1 = 0.f;
        if (t < Lout) {
            v0 = hb[(size_t)t * NRES + c];
            v1 = hb[(size_t)(t + d) * NRES + c];
        }
        hs0f[c * (2 * HS_STRIDE) + j] = v0;
        hs1f[c * (2 * HS_STRIDE) + j] = v1;
    }
    __syncthreads();

    int w = tid >> 5, o = tid & 31;
    int jp0 = w * 6;                       // this warp's first time-pair

    float2 ps[6], pt[6];
#pragma unroll
    for (int p = 0; p < 6; ++p) {
        ps[p] = f2(bs[o], bs[o]);
        pt[p] = f2(bt[o], bt[o]);
    }

#pragma unroll 4
    for (int c = 0; c < 32; ++c) {
        float4 Ws = wsd[c * 32 + o];       // W0,W0,W1,W1
        float4 Wt = wtd[c * 32 + o];       // V0,V0,V1,V1
        const float4* ap = reinterpret_cast<const float4*>(&hs0[c * HS_STRIDE + jp0]);
        const float4* ep = reinterpret_cast<const float4*>(&hs1[c * HS_STRIDE + jp0]);
        float4 A0 = ap[0], A1 = ap[1], A2 = ap[2];
        float4 E0 = ep[0], E1 = ep[1], E2 = ep[2];
        float2 w0 = f2(Ws.x, Ws.y), w1 = f2(Ws.z, Ws.w);
        float2 v0 = f2(Wt.x, Wt.y), v1 = f2(Wt.z, Wt.w);
        ps[0] = ffma2(w0, f2(A0.x, A0.y), ps[0]); ps[0] = ffma2(w1, f2(E0.x, E0.y), ps[0]);
        ps[1] = ffma2(w0, f2(A0.z, A0.w), ps[1]); ps[1] = ffma2(w1, f2(E0.z, E0.w), ps[1]);
        ps[2] = ffma2(w0, f2(A1.x, A1.y), ps[2]); ps[2] = ffma2(w1, f2(E1.x, E1.y), ps[2]);
        ps[3] = ffma2(w0, f2(A1.z, A1.w), ps[3]); ps[3] = ffma2(w1, f2(E1.z, E1.w), ps[3]);
        ps[4] = ffma2(w0, f2(A2.x, A2.y), ps[4]); ps[4] = ffma2(w1, f2(E2.x, E2.y), ps[4]);
        ps[5] = ffma2(w0, f2(A2.z, A2.w), ps[5]); ps[5] = ffma2(w1, f2(E2.z, E2.w), ps[5]);
        pt[0] = ffma2(v0, f2(A0.x, A0.y), pt[0]); pt[0] = ffma2(v1, f2(E0.x, E0.y), pt[0]);
        pt[1] = ffma2(v0, f2(A0.z, A0.w), pt[1]); pt[1] = ffma2(v1, f2(E0.z, E0.w), pt[1]);
        pt[2] = ffma2(v0, f2(A1.x, A1.y), pt[2]); pt[2] = ffma2(v1, f2(E1.x, E1.y), pt[2]);
        pt[3] = ffma2(v0, f2(A1.z, A1.w), pt[3]); pt[3] = ffma2(v1, f2(E1.z, E1.w), pt[3]);
        pt[4] = ffma2(v0, f2(A2.x, A2.y), pt[4]); pt[4] = ffma2(v1, f2(E2.x, E2.y), pt[4]);
        pt[5] = ffma2(v0, f2(A2.z, A2.w), pt[5]); pt[5] = ffma2(v1, f2(E2.z, E2.w), pt[5]);
    }

    // gated activation
    float2 g[6];
#pragma unroll
    for (int p = 0; p < 6; ++p) {
        g[p].x = sigmoid_f(ps[p].x) * tanh_f(pt[p].x);
        g[p].y = sigmoid_f(ps[p].y) * tanh_f(pt[p].y);
    }

    // residual init: br + h[t+d] (own channel), read BEFORE hs0 is reused
    float2 r[6];
#pragma unroll
    for (int p = 0; p < 6; ++p) {
        float2 h1o = hs1[o * HS_STRIDE + jp0 + p];
        r[p] = f2(br[o] + h1o.x, br[o] + h1o.y);
    }

    // stash g into hs0's warp-private columns (hs0 is dead for this warp now)
#pragma unroll
    for (int p = 0; p < 6; ++p) hs0[o * HS_STRIDE + jp0 + p] = g[p];
    __syncwarp();

    // res matvec: r += Wr * g  (broadcast reads of warp-private g columns)
#pragma unroll 4
    for (int c = 0; c < 32; ++c) {
        float2 wv = wrd[c * 32 + o];
        const float4* gp = reinterpret_cast<const float4*>(&hs0[c * HS_STRIDE + jp0]);
        float4 G0 = gp[0], G1 = gp[1], G2 = gp[2];
        r[0] = ffma2(wv, f2(G0.x, G0.y), r[0]);
        r[1] = ffma2(wv, f2(G0.z, G0.w), r[1]);
        r[2] = ffma2(wv, f2(G1.x, G1.y), r[2]);
        r[3] = ffma2(wv, f2(G1.z, G1.w), r[3]);
        r[4] = ffma2(wv, f2(G2.x, G2.y), r[4]);
        r[5] = ffma2(wv, f2(G2.z, G2.w), r[5]);
    }

    // stores
    float* Gb  = g_G + (size_t)b * OUTLEN * (NLAY * NRES) + (size_t)layer * NRES;
    float* hob = h_out + (size_t)b * T_LEN * NRES;
#pragma unroll
    for (int p = 0; p < 6; ++p) {
        int t = t0 + w * 12 + 2 * p;
        if (t < Lout) {
            hob[(size_t)t * NRES + o] = r[p].x;
            int u = t - goff;
            if (u >= 0) Gb[(size_t)u * (NLAY * NRES) + o] = g[p].x;
        }
        if (t + 1 < Lout) {
            hob[(size_t)(t + 1) * NRES + o] = r[p].y;
            int u = t + 1 - goff;
            if (u >= 0) Gb[(size_t)u * (NLAY * NRES) + o] = g[p].y;
        }
    }
}

// ------------------------------ GEMM core ----------------------------------
// C[M x 512] = A[M x KDIM] * B[KDIM x 512] (+bias). BM=128, BN=64, BK=16,
// 256 threads, 8m x 4n per thread via FFMA2, double-buffered smem with
// register-staged global prefetch.
template <int KDIM, bool ELU_IN, bool ELU_OUT>
__device__ __forceinline__ void gemm_core(
    const float* __restrict__ A, const float* __restrict__ Bm,
    const float* __restrict__ bias, float* __restrict__ Cout, int M)
{
    const int N = 512;
    __shared__ float  As[2][16][128];
    __shared__ float2 Bsd[2][16][64];

    int tid = threadIdx.x;
    int mBase = blockIdx.x * 128;
    int nBase = blockIdx.y * 64;
    int m0 = (tid & 15) * 8;
    int n0 = (tid >> 4) * 4;

    int ar = tid >> 1;            // 0..127
    int ac = (tid & 1) * 8;       // 0 or 8
    int bk = tid >> 4;            // 0..15
    int bn = (tid & 15) * 4;      // 0..60

    int row = mBase + ar;
    bool rowOK = row < M;
    const float* Aptr = A + (size_t)row * KDIM + ac;
    const float* Bptr = Bm + (size_t)bk * N + nBase + bn;

    float2 acc[4][4];
#pragma unroll
    for (int i = 0; i < 4; ++i)
#pragma unroll
        for (int j = 0; j < 4; ++j) acc[i][j] = make_float2(0.f, 0.f);

    float4 av0, av1, bv;

    auto fetch = [&](int kt) {
        if (rowOK) {
            av0 = *reinterpret_cast<const float4*>(Aptr + kt);
            av1 = *reinterpret_cast<const float4*>(Aptr + kt + 4);
        } else {
            av0 = make_float4(0.f, 0.f, 0.f, 0.f);
            av1 = av0;
        }
        bv = *reinterpret_cast<const float4*>(Bptr + (size_t)kt * N);
    };
    auto stage = [&](int s) {
        float4 u0 = av0, u1 = av1;
        if (ELU_IN) {
            u0.x = eluf(u0.x); u0.y = eluf(u0.y); u0.z = eluf(u0.z); u0.w = eluf(u0.w);
            u1.x = eluf(u1.x); u1.y = eluf(u1.y); u1.z = eluf(u1.z); u1.w = eluf(u1.w);
        }
        As[s][ac + 0][ar] = u0.x; As[s][ac + 1][ar] = u0.y;
        As[s][ac + 2][ar] = u0.z; As[s][ac + 3][ar] = u0.w;
        As[s][ac + 4][ar] = u1.x; As[s][ac + 5][ar] = u1.y;
        As[s][ac + 6][ar] = u1.z; As[s][ac + 7][ar] = u1.w;
        float4* bd = reinterpret_cast<float4*>(&Bsd[s][bk][bn]);
        bd[0] = make_float4(bv.x, bv.x, bv.y, bv.y);
        bd[1] = make_float4(bv.z, bv.z, bv.w, bv.w);
    };

    const int nt = KDIM / 16;
    fetch(0);
    stage(0);
    __syncthreads();

    for (int t = 0; t < nt; ++t) {
        int cur = t & 1;
        if (t + 1 < nt) fetch((t + 1) * 16);
#pragma unroll
        for (int k = 0; k < 16; ++k) {
            float4 a0 = *reinterpret_cast<const float4*>(&As[cur][k][m0]);
            float4 a1 = *reinterpret_cast<const float4*>(&As[cur][k][m0 + 4]);
            float4 b0 = *reinterpret_cast<const float4*>(&Bsd[cur][k][n0]);
            float4 b1 = *reinterpret_cast<const float4*>(&Bsd[cur][k][n0 + 2]);
            float2 ap[4] = { {a0.x, a0.y}, {a0.z, a0.w}, {a1.x, a1.y}, {a1.z, a1.w} };
            float2 bq[4] = { {b0.x, b0.y}, {b0.z, b0.w}, {b1.x, b1.y}, {b1.z, b1.w} };
#pragma unroll
            for (int i = 0; i < 4; ++i)
#pragma unroll
                for (int j = 0; j < 4; ++j)
                    acc[i][j] = ffma2(ap[i], bq[j], acc[i][j]);
        }
        if (t + 1 < nt) stage(1 - cur);
        __syncthreads();
    }

    float b4[4];
#pragma unroll
    for (int j = 0; j < 4; ++j) b4[j] = bias[nBase + n0 + j];

#pragma unroll
    for (int i = 0; i < 4; ++i) {
        int r0 = mBase + m0 + 2 * i;
        float4 o0 = make_float4(acc[i][0].x + b4[0], acc[i][1].x + b4[1],
                                acc[i][2].x + b4[2], acc[i][3].x + b4[3]);
        float4 o1 = make_float4(acc[i][0].y + b4[0], acc[i][1].y + b4[1],
                                acc[i][2].y + b4[2], acc[i][3].y + b4[3]);
        if (ELU_OUT) {
            o0.x = eluf(o0.x); o0.y = eluf(o0.y); o0.z = eluf(o0.z); o0.w = eluf(o0.w);
            o1.x = eluf(o1.x); o1.y = eluf(o1.y); o1.z = eluf(o1.z); o1.w = eluf(o1.w);
        }
        if (r0 < M)
            *reinterpret_cast<float4*>(Cout + (size_t)r0 * 512 + nBase + n0) = o0;
        if (r0 + 1 < M)
            *reinterpret_cast<float4*>(Cout + (size_t)(r0 + 1) * 512 + nBase + n0) = o1;
    }
}

__global__ __launch_bounds__(256) void skip_gemm_kernel(int M)
{
    gemm_core<NLAY * NRES, false, false>(g_G, g_Wskip, g_bskip, g_skip, M);
}
__global__ __launch_bounds__(256) void post1_gemm_kernel(const float* __restrict__ b_post1, int M)
{
    gemm_core<NSKIP, true, true>(g_skip, g_Wp1T, b_post1, g_y2, M);
}

// ------------------------------ post2 --------------------------------------
__global__ __launch_bounds__(256) void post2_kernel(
    const float* __restrict__ w2, const float* __restrict__ b2,
    float* __restrict__ out, int M)
{
    int gw = (blockIdx.x * 256 + threadIdx.x) >> 5;
    int lane = threadIdx.x & 31;
    if (gw >= M) return;
    const float* row = g_y2 + (size_t)gw * NSKIP;
    float acc = 0.f;
#pragma unroll
    for (int k = 0; k < 16; ++k)
        acc = fmaf(row[lane + 32 * k], w2[lane + 32 * k], acc);
#pragma unroll
    for (int s = 16; s > 0; s >>= 1)
        acc += __shfl_xor_sync(0xffffffffu, acc, s);
    if (lane == 0) out[gw] = acc + b2[0];
}

// ------------------------------ launch -------------------------------------
extern "C" void kernel_launch(void* const* d_in, const int* in_sizes, int n_in,
                              void* d_out, int out_size)
{
    const float* x       = (const float*)d_in[0];
    const float* w_in    = (const float*)d_in[1];
    const float* b_in    = (const float*)d_in[2];
    const float* w_sig   = (const float*)d_in[3];
    const float* b_sig   = (const float*)d_in[4];
    const float* w_tanh  = (const float*)d_in[5];
    const float* b_tanh  = (const float*)d_in[6];
    const float* w_skip  = (const float*)d_in[7];
    const float* b_skip  = (const float*)d_in[8];
    const float* w_res   = (const float*)d_in[9];
    const float* b_res   = (const float*)d_in[10];
    const float* w_post1 = (const float*)d_in[11];
    const float* b_post1 = (const float*)d_in[12];
    const float* w_post2 = (const float*)d_in[13];
    const float* b_post2 = (const float*)d_in[14];
    float* out = (float*)d_out;

    cudaFuncSetAttribute(layer_kernel,
                         cudaFuncAttributeMaxDynamicSharedMemorySize, LK_SMEM);

    in_conv_kernel<<<dim3(T_LEN / 8, BATCH), 256>>>(x, w_in, b_in);

    repack_wskip_kernel<<<(NLAY * NRES * NSKIP) / 256, 256>>>(w_skip);
    bias_sum_kernel<<<2, 256>>>(b_skip);
    repack_wpost1_kernel<<<(NSKIP * NSKIP) / 256, 256>>>(w_post1);

    static const int dil10[10] = {1, 2, 4, 8, 16, 32, 64, 128, 256, 512};
    int L = T_LEN;
    for (int i = 0; i < NLAY; ++i) {
        int d = dil10[i % 10];
        int Lout = L - d;
        int goff = Lout - OUTLEN;
        int nb = (Lout + LTS - 1) / LTS;
        layer_kernel<<<dim3(nb, BATCH), 256, LK_SMEM>>>(
            w_sig, b_sig, w_tanh, b_tanh, w_res, b_res, i, d, Lout, goff, i & 1);
        L = Lout;
    }

    int M = MROWS;
    dim3 ggrid((M + 127) / 128, NSKIP / 64);
    skip_gemm_kernel<<<ggrid, 256>>>(M);
    post1_gemm_kernel<<<ggrid, 256>>>(b_post1, M);
    post2_kernel<<<(M + 7) / 8, 256>>>(w_post2, b_post2, out, M);
}

// round 8
// speedup vs baseline: 1.9415x; 1.8972x over previous
#include <cuda_runtime.h>
#include <cstdint>
#include <cstddef>

// ---------------------------------------------------------------------------
// WaveNet forward.  Layers: fp32 FFMA2 kernels (proven).  Skip + post1 GEMMs:
// warp mma.sync m16n8k8 tf32 (portable PTX), plain-padded SMEM tiles, PTX-ISA
// fragment gathers, double buffered, fused bias+ELU epilogue.
// CRITICAL FIX vs R6/R7: device-global buffers are referenced from DEVICE
// code (wrapper kernels), never passed as host-side kernel arguments.
// ---------------------------------------------------------------------------

#define T_LEN   8192
#define NRES    32
#define NSKIP   512
#define NFEAT   8
#define NLAY    50
#define OUTLEN  3077
#define BATCH   8
#define LTS     96
#define MROWS   (BATCH * OUTLEN)      // 24616
#define KSKIP   (NLAY * NRES)         // 1600

// ------------------------- device scratch (static) -------------------------
__device__ float g_hA[(size_t)BATCH * T_LEN * NRES];
__device__ float g_hB[(size_t)BATCH * T_LEN * NRES];
__device__ float g_G[(size_t)MROWS * KSKIP];                // [row][k], K-major
__device__ float g_skip[(size_t)MROWS * NSKIP];             // elu(skip_sum+bias)
__device__ float g_y2[(size_t)MROWS * NSKIP];               // elu(post1 out)
__device__ float g_WskipT[(size_t)NSKIP * KSKIP];           // [s][k], K-major
__device__ float g_bskip[NSKIP];

// ------------------------------ helpers ------------------------------------
__device__ __forceinline__ uint32_t f2tf(float x) {
    uint32_t r;
    asm("cvt.rna.tf32.f32 %0, %1;" : "=r"(r) : "f"(x));
    return r;
}
__device__ __forceinline__ float2 ffma2(float2 a, float2 b, float2 c) {
    float2 d;
    asm("fma.rn.f32x2 %0, %1, %2, %3;"
        : "=l"(*reinterpret_cast<unsigned long long*>(&d))
        : "l"(*reinterpret_cast<unsigned long long*>(&a)),
          "l"(*reinterpret_cast<unsigned long long*>(&b)),
          "l"(*reinterpret_cast<unsigned long long*>(&c)));
    return d;
}
__device__ __forceinline__ float2 f2(float x, float y) { return make_float2(x, y); }
__device__ __forceinline__ float sigmoid_f(float x) {
    x = fminf(fmaxf(x, -30.f), 30.f);
    return __fdividef(1.f, 1.f + __expf(-x));
}
__device__ __forceinline__ float tanh_f(float x) {
    x = fminf(fmaxf(x, -15.f), 15.f);
    float e = __expf(-2.f * x);
    return __fdividef(1.f - e, 1.f + e);
}
__device__ __forceinline__ float eluf(float x) {
    return x > 0.f ? x : (__expf(x) - 1.f);
}

// ------------------------------ input conv ---------------------------------
__global__ __launch_bounds__(256) void in_conv_kernel(
    const float* __restrict__ x, const float* __restrict__ w_in,
    const float* __restrict__ b_in)
{
    int b = blockIdx.y;
    int t = blockIdx.x * 8 + (threadIdx.x >> 5);
    int o = threadIdx.x & 31;
    float w[NFEAT];
#pragma unroll
    for (int f = 0; f < NFEAT; ++f) w[f] = w_in[o * NFEAT + f];
    const float* xp = x + ((size_t)b * T_LEN + t) * NFEAT;
    float acc = b_in[o];
#pragma unroll
    for (int f = 0; f < NFEAT; ++f) acc = fmaf(w[f], xp[f], acc);
    g_hA[((size_t)b * T_LEN + t) * NRES + o] = acc;
}

// ------------------------------ repacks ------------------------------------
// g_WskipT[s][k] = w_skip[i][s][c], k = i*32+c
__global__ __launch_bounds__(256) void repack_wskipT_kernel(const float* __restrict__ w_skip)
{
    int idx = blockIdx.x * 256 + threadIdx.x;       // < 512*1600
    int s = idx / KSKIP, k = idx - s * KSKIP;
    g_WskipT[idx] = w_skip[(size_t)(k >> 5) * (NSKIP * NRES) + (size_t)s * NRES + (k & 31)];
}
__global__ __launch_bounds__(256) void bias_sum_kernel(const float* __restrict__ b_skip)
{
    int s = blockIdx.x * 256 + threadIdx.x;
    if (s < NSKIP) {
        float a = 0.f;
#pragma unroll
        for (int i = 0; i < NLAY; ++i) a += b_skip[i * NSKIP + s];
        g_bskip[s] = a;
    }
}

// ------------------------------ layer kernel (unchanged) -------------------
#define LK_SMEM 66944
#define HS_STRIDE 50

__global__ __launch_bounds__(256) void layer_kernel(
    const float* __restrict__ w_sig, const float* __restrict__ b_sig,
    const float* __restrict__ w_tanh, const float* __restrict__ b_tanh,
    const float* __restrict__ w_res, const float* __restrict__ b_res,
    int layer, int d, int Lout, int goff, int ping)
{
    extern __shared__ char smraw[];
    float4* wsd = reinterpret_cast<float4*>(smraw);
    float4* wtd = reinterpret_cast<float4*>(smraw + 16384);
    float2* wrd = reinterpret_cast<float2*>(smraw + 32768);
    float2* hs0 = reinterpret_cast<float2*>(smraw + 40960);
    float2* hs1 = reinterpret_cast<float2*>(smraw + 53760);
    float*  bs  = reinterpret_cast<float*>(smraw + 66560);
    float*  bt  = bs + 32;
    float*  br  = bs + 64;

    const float* h_in = ping ? g_hB : g_hA;
    float* h_out      = ping ? g_hA : g_hB;

    int tid = threadIdx.x;
    int b = blockIdx.y;
    int t0 = blockIdx.x * LTS;

    const float* wsp = w_sig  + (size_t)layer * 2048;
    const float* wtp = w_tanh + (size_t)layer * 2048;
    const float* wrp = w_res  + (size_t)layer * 1024;
#pragma unroll
    for (int p = tid; p < 1024; p += 256) {
        int o = p & 31, c = p >> 5;
        float s0 = wsp[(o * 32 + c) * 2], s1 = wsp[(o * 32 + c) * 2 + 1];
        wsd[c * 32 + o] = make_float4(s0, s0, s1, s1);
        float u0 = wtp[(o * 32 + c) * 2], u1 = wtp[(o * 32 + c) * 2 + 1];
        wtd[c * 32 + o] = make_float4(u0, u0, u1, u1);
        float r = wrp[o * 32 + c];
        wrd[c * 32 + o] = make_float2(r, r);
    }
    if (tid < 32) {
        bs[tid] = b_sig[layer * 32 + tid];
        bt[tid] = b_tanh[layer * 32 + tid];
        br[tid] = b_res[layer * 32 + tid];
    }

    const float* hb = h_in + (size_t)b * T_LEN * NRES;
    float* hs0f = reinterpret_cast<float*>(hs0);
    float* hs1f = reinterpret_cast<float*>(hs1);
    for (int idx = tid; idx < LTS * 32; idx += 256) {
        int j = idx >> 5, c = idx & 31;
        int t = t0 + j;
        float v0 = 0.f, v1 = 0.f;
        if (t < Lout) {
            v0 = hb[(size_t)t * NRES + c];
            v1 = hb[(size_t)(t + d) * NRES + c];
        }
        hs0f[c * (2 * HS_STRIDE) + j] = v0;
        hs1f[c * (2 * HS_STRIDE) + j] = v1;
    }
    __syncthreads();

    int w = tid >> 5, o = tid & 31;
    int jp0 = w * 6;

    float2 ps[6], pt[6];
#pragma unroll
    for (int p = 0; p < 6; ++p) {
        ps[p] = f2(bs[o], bs[o]);
        pt[p] = f2(bt[o], bt[o]);
    }

#pragma unroll 4
    for (int c = 0; c < 32; ++c) {
        float4 Ws = wsd[c * 32 + o];
        float4 Wt = wtd[c * 32 + o];
        const float4* ap = reinterpret_cast<const float4*>(&hs0[c * HS_STRIDE + jp0]);
        const float4* ep = reinterpret_cast<const float4*>(&hs1[c * HS_STRIDE + jp0]);
        float4 A0 = ap[0], A1 = ap[1], A2 = ap[2];
        float4 E0 = ep[0], E1 = ep[1], E2 = ep[2];
        float2 w0 = f2(Ws.x, Ws.y), w1 = f2(Ws.z, Ws.w);
        float2 v0 = f2(Wt.x, Wt.y), v1 = f2(Wt.z, Wt.w);
        ps[0] = ffma2(w0, f2(A0.x, A0.y), ps[0]); ps[0] = ffma2(w1, f2(E0.x, E0.y), ps[0]);
        ps[1] = ffma2(w0, f2(A0.z, A0.w), ps[1]); ps[1] = ffma2(w1, f2(E0.z, E0.w), ps[1]);
        ps[2] = ffma2(w0, f2(A1.x, A1.y), ps[2]); ps[2] = ffma2(w1, f2(E1.x, E1.y), ps[2]);
        ps[3] = ffma2(w0, f2(A1.z, A1.w), ps[3]); ps[3] = ffma2(w1, f2(E1.z, E1.w), ps[3]);
        ps[4] = ffma2(w0, f2(A2.x, A2.y), ps[4]); ps[4] = ffma2(w1, f2(E2.x, E2.y), ps[4]);
        ps[5] = ffma2(w0, f2(A2.z, A2.w), ps[5]); ps[5] = ffma2(w1, f2(E2.z, E2.w), ps[5]);
        pt[0] = ffma2(v0, f2(A0.x, A0.y), pt[0]); pt[0] = ffma2(v1, f2(E0.x, E0.y), pt[0]);
        pt[1] = ffma2(v0, f2(A0.z, A0.w), pt[1]); pt[1] = ffma2(v1, f2(E0.z, E0.w), pt[1]);
        pt[2] = ffma2(v0, f2(A1.x, A1.y), pt[2]); pt[2] = ffma2(v1, f2(E1.x, E1.y), pt[2]);
        pt[3] = ffma2(v0, f2(A1.z, A1.w), pt[3]); pt[3] = ffma2(v1, f2(E1.z, E1.w), pt[3]);
        pt[4] = ffma2(v0, f2(A2.x, A2.y), pt[4]); pt[4] = ffma2(v1, f2(E2.x, E2.y), pt[4]);
        pt[5] = ffma2(v0, f2(A2.z, A2.w), pt[5]); pt[5] = ffma2(v1, f2(E2.z, E2.w), pt[5]);
    }

    float2 g[6];
#pragma unroll
    for (int p = 0; p < 6; ++p) {
        g[p].x = sigmoid_f(ps[p].x) * tanh_f(pt[p].x);
        g[p].y = sigmoid_f(ps[p].y) * tanh_f(pt[p].y);
    }

    float2 r[6];
#pragma unroll
    for (int p = 0; p < 6; ++p) {
        float2 h1o = hs1[o * HS_STRIDE + jp0 + p];
        r[p] = f2(br[o] + h1o.x, br[o] + h1o.y);
    }

#pragma unroll
    for (int p = 0; p < 6; ++p) hs0[o * HS_STRIDE + jp0 + p] = g[p];
    __syncwarp();

#pragma unroll 4
    for (int c = 0; c < 32; ++c) {
        float2 wv = wrd[c * 32 + o];
        const float4* gp = reinterpret_cast<const float4*>(&hs0[c * HS_STRIDE + jp0]);
        float4 G0 = gp[0], G1 = gp[1], G2 = gp[2];
        r[0] = ffma2(wv, f2(G0.x, G0.y), r[0]);
        r[1] = ffma2(wv, f2(G0.z, G0.w), r[1]);
        r[2] = ffma2(wv, f2(G1.x, G1.y), r[2]);
        r[3] = ffma2(wv, f2(G1.z, G1.w), r[3]);
        r[4] = ffma2(wv, f2(G2.x, G2.y), r[4]);
        r[5] = ffma2(wv, f2(G2.z, G2.w), r[5]);
    }

    float* Gb  = g_G + (size_t)b * OUTLEN * KSKIP + (size_t)layer * NRES;
    float* hob = h_out + (size_t)b * T_LEN * NRES;
#pragma unroll
    for (int p = 0; p < 6; ++p) {
        int t = t0 + w * 12 + 2 * p;
        if (t < Lout) {
            hob[(size_t)t * NRES + o] = r[p].x;
            int u = t - goff;
            if (u >= 0) Gb[(size_t)u * KSKIP + o] = g[p].x;
        }
        if (t + 1 < Lout) {
            hob[(size_t)(t + 1) * NRES + o] = r[p].y;
            int u = t + 1 - goff;
            if (u >= 0) Gb[(size_t)u * KSKIP + o] = g[p].y;
        }
    }
}

// ------------------------- mma.sync tf32 GEMM core -------------------------
// C[M x 512] = elu(A[M x KDIM] * B[512 x KDIM]^T + bias).
// BM=128, BN=128, BK=32, 256 threads (8 warps: 2m x 4n), per warp 4x4
// m16n8k8 tiles.  SMEM: plain row-major [128][32] padded to stride 36.
// Fragment gathers use the PTX ISA (row,col) formulas directly.
#define GPAD 36
#define GTILE (128 * GPAD)                 // 4608 floats per tile
#define GSM_BYTES (2 * 2 * GTILE * 4)      // 73728 bytes

template <int KDIM>
__device__ __forceinline__ void mma_gemm_core(
    const float* __restrict__ A, const float* __restrict__ B,
    const float* __restrict__ bias, float* __restrict__ C, int M)
{
    extern __shared__ float sm[];
    int tid = threadIdx.x;
    int wid = tid >> 5, lane = tid & 31;
    int g = lane >> 2, tg = lane & 3;
    int nBase = blockIdx.x * 128;      // n fastest -> 4 n-blocks share A in L2
    int mBase = blockIdx.y * 128;
    int mwarp = wid >> 2, nwarp = wid & 3;

    float acc[4][4][4] = {};

    float4 aR[4], bR[4];
    auto fetch = [&](int kt) {
#pragma unroll
        for (int i = 0; i < 4; ++i) {
            int gg = tid + i * 256;
            int row = gg >> 3, c4 = gg & 7;
            int gr = mBase + row;
            aR[i] = (gr < M)
                ? *reinterpret_cast<const float4*>(A + (size_t)gr * KDIM + kt + c4 * 4)
                : make_float4(0.f, 0.f, 0.f, 0.f);
            bR[i] = *reinterpret_cast<const float4*>(
                B + (size_t)(nBase + row) * KDIM + kt + c4 * 4);
        }
    };
    auto stage = [&](int buf) {
        float* Ab = sm + buf * (2 * GTILE);
        float* Bb = Ab + GTILE;
#pragma unroll
        for (int i = 0; i < 4; ++i) {
            int gg = tid + i * 256;
            int row = gg >> 3, c4 = gg & 7;
            int base = row * GPAD + c4 * 4;
            Ab[base + 0] = __uint_as_float(f2tf(aR[i].x));
            Ab[base + 1] = __uint_as_float(f2tf(aR[i].y));
            Ab[base + 2] = __uint_as_float(f2tf(aR[i].z));
            Ab[base + 3] = __uint_as_float(f2tf(aR[i].w));
            Bb[base + 0] = __uint_as_float(f2tf(bR[i].x));
            Bb[base + 1] = __uint_as_float(f2tf(bR[i].y));
            Bb[base + 2] = __uint_as_float(f2tf(bR[i].z));
            Bb[base + 3] = __uint_as_float(f2tf(bR[i].w));
        }
    };
    auto compute = [&](int buf) {
        const float* Ab = sm + buf * (2 * GTILE);
        const float* Bb = Ab + GTILE;
#pragma unroll
        for (int ks = 0; ks < 4; ++ks) {
            int k0 = ks * 8;
            uint32_t af[4][4];
#pragma unroll
            for (int mt = 0; mt < 4; ++mt) {
                int r = mwarp * 64 + mt * 16 + g;
                af[mt][0] = __float_as_uint(Ab[r * GPAD + k0 + tg]);
                af[mt][1] = __float_as_uint(Ab[(r + 8) * GPAD + k0 + tg]);
                af[mt][2] = __float_as_uint(Ab[r * GPAD + k0 + tg + 4]);
                af[mt][3] = __float_as_uint(Ab[(r + 8) * GPAD + k0 + tg + 4]);
            }
            uint32_t bf[4][2];
#pragma unroll
            for (int nt2 = 0; nt2 < 4; ++nt2) {
                int n = nwarp * 32 + nt2 * 8 + g;
                bf[nt2][0] = __float_as_uint(Bb[n * GPAD + k0 + tg]);
                bf[nt2][1] = __float_as_uint(Bb[n * GPAD + k0 + tg + 4]);
            }
#pragma unroll
            for (int mt = 0; mt < 4; ++mt)
#pragma unroll
                for (int nt2 = 0; nt2 < 4; ++nt2)
                    asm volatile(
                        "mma.sync.aligned.m16n8k8.row.col.f32.tf32.tf32.f32 "
                        "{%0,%1,%2,%3}, {%4,%5,%6,%7}, {%8,%9}, {%0,%1,%2,%3};"
                        : "+f"(acc[mt][nt2][0]), "+f"(acc[mt][nt2][1]),
                          "+f"(acc[mt][nt2][2]), "+f"(acc[mt][nt2][3])
                        : "r"(af[mt][0]), "r"(af[mt][1]), "r"(af[mt][2]), "r"(af[mt][3]),
                          "r"(bf[nt2][0]), "r"(bf[nt2][1]));
        }
    };

    const int nt = KDIM / 32;
    fetch(0);
    stage(0);
    __syncthreads();
    for (int t = 0; t < nt; ++t) {
        int cur = t & 1;
        if (t + 1 < nt) fetch((t + 1) * 32);
        compute(cur);
        if (t + 1 < nt) stage(1 - cur);
        __syncthreads();
    }

    // epilogue: bias + elu
    int cbase = nBase + nwarp * 32;
#pragma unroll
    for (int nt2 = 0; nt2 < 4; ++nt2) {
        int col = cbase + nt2 * 8 + tg * 2;
        float b0 = bias[col], b1 = bias[col + 1];
#pragma unroll
        for (int mt = 0; mt < 4; ++mt) {
            int r0 = mBase + mwarp * 64 + mt * 16 + g;
            int r1 = r0 + 8;
            if (r0 < M) {
                float2 v;
                v.x = eluf(acc[mt][nt2][0] + b0);
                v.y = eluf(acc[mt][nt2][1] + b1);
                *reinterpret_cast<float2*>(C + (size_t)r0 * NSKIP + col) = v;
            }
            if (r1 < M) {
                float2 v;
                v.x = eluf(acc[mt][nt2][2] + b0);
                v.y = eluf(acc[mt][nt2][3] + b1);
                *reinterpret_cast<float2*>(C + (size_t)r1 * NSKIP + col) = v;
            }
        }
    }
}

// Wrapper kernels: device-global pointers are formed in DEVICE code.
__global__ __launch_bounds__(256) void skip_gemm_kernel(int M)
{
    mma_gemm_core<KSKIP>(g_G, g_WskipT, g_bskip, g_skip, M);
}
__global__ __launch_bounds__(256) void post1_gemm_kernel(
    const float* __restrict__ w_post1, const float* __restrict__ b_post1, int M)
{
    mma_gemm_core<NSKIP>(g_skip, w_post1, b_post1, g_y2, M);
}

// ------------------------------ post2 --------------------------------------
__global__ __launch_bounds__(256) void post2_kernel(
    const float* __restrict__ w2, const float* __restrict__ b2,
    float* __restrict__ out, int M)
{
    int gw = (blockIdx.x * 256 + threadIdx.x) >> 5;
    int lane = threadIdx.x & 31;
    if (gw >= M) return;
    const float* row = g_y2 + (size_t)gw * NSKIP;
    float acc = 0.f;
#pragma unroll
    for (int k = 0; k < 16; ++k)
        acc = fmaf(row[lane + 32 * k], w2[lane + 32 * k], acc);
#pragma unroll
    for (int s = 16; s > 0; s >>= 1)
        acc += __shfl_xor_sync(0xffffffffu, acc, s);
    if (lane == 0) out[gw] = acc + b2[0];
}

// ------------------------------ launch -------------------------------------
extern "C" void kernel_launch(void* const* d_in, const int* in_sizes, int n_in,
                              void* d_out, int out_size)
{
    const float* x       = (const float*)d_in[0];
    const float* w_in    = (const float*)d_in[1];
    const float* b_in    = (const float*)d_in[2];
    const float* w_sig   = (const float*)d_in[3];
    const float* b_sig   = (const float*)d_in[4];
    const float* w_tanh  = (const float*)d_in[5];
    const float* b_tanh  = (const float*)d_in[6];
    const float* w_skip  = (const float*)d_in[7];
    const float* b_skip  = (const float*)d_in[8];
    const float* w_res   = (const float*)d_in[9];
    const float* b_res   = (const float*)d_in[10];
    const float* w_post1 = (const float*)d_in[11];
    const float* b_post1 = (const float*)d_in[12];
    const float* w_post2 = (const float*)d_in[13];
    const float* b_post2 = (const float*)d_in[14];
    float* out = (float*)d_out;

    cudaFuncSetAttribute(layer_kernel,
                         cudaFuncAttributeMaxDynamicSharedMemorySize, LK_SMEM);
    cudaFuncSetAttribute(skip_gemm_kernel,
                         cudaFuncAttributeMaxDynamicSharedMemorySize, GSM_BYTES);
    cudaFuncSetAttribute(post1_gemm_kernel,
                         cudaFuncAttributeMaxDynamicSharedMemorySize, GSM_BYTES);

    in_conv_kernel<<<dim3(T_LEN / 8, BATCH), 256>>>(x, w_in, b_in);

    repack_wskipT_kernel<<<(NSKIP * KSKIP) / 256, 256>>>(w_skip);
    bias_sum_kernel<<<2, 256>>>(b_skip);

    static const int dil10[10] = {1, 2, 4, 8, 16, 32, 64, 128, 256, 512};
    int L = T_LEN;
    for (int i = 0; i < NLAY; ++i) {
        int d = dil10[i % 10];
        int Lout = L - d;
        int goff = Lout - OUTLEN;
        int nb = (Lout + LTS - 1) / LTS;
        layer_kernel<<<dim3(nb, BATCH), 256, LK_SMEM>>>(
            w_sig, b_sig, w_tanh, b_tanh, w_res, b_res, i, d, Lout, goff, i & 1);
        L = Lout;
    }

    int M = MROWS;
    dim3 ggrid(NSKIP / 128, (M + 127) / 128);   // n fastest for A reuse in L2
    skip_gemm_kernel<<<ggrid, 256, GSM_BYTES>>>(M);
    post1_gemm_kernel<<<ggrid, 256, GSM_BYTES>>>(w_post1, b_post1, M);
    post2_kernel<<<(M + 7) / 8, 256>>>(w_post2, b_post2, out, M);
}